// round 12
// baseline (speedup 1.0000x reference)
#include <cuda_runtime.h>

#define BB 512
#define SS 512
#define CC 96
#define TEAMS 2
#define TEAM_THREADS CC                      // 96 threads: 48 col-pairs x 2 halves
#define FWD_THREADS (TEAMS * TEAM_THREADS)   // 192

typedef unsigned long long u64;

__device__ float g_num[BB];
__device__ float g_den[BB];

// ---- f32x2 packed helpers (sm_103a) ----
__device__ __forceinline__ u64 pack2(float x, float y) {
    u64 r;
    asm("mov.b64 %0, {%1, %2};" : "=l"(r) : "r"(__float_as_int(x)), "r"(__float_as_int(y)));
    return r;
}
__device__ __forceinline__ float2 unpack2(u64 v) {
    int lo, hi;
    asm("mov.b64 {%0, %1}, %2;" : "=r"(lo), "=r"(hi) : "l"(v));
    float2 f; f.x = __int_as_float(lo); f.y = __int_as_float(hi);
    return f;
}
__device__ __forceinline__ void fmadd2(u64& d, u64 a, u64 b) {
    asm("fma.rn.f32x2 %0, %1, %2, %0;" : "+l"(d) : "l"(a), "l"(b));
}
__device__ __forceinline__ u64 add2(u64 a, u64 b) {
    u64 r;
    asm("add.rn.f32x2 %0, %1, %2;" : "=l"(r) : "l"(a), "l"(b));
    return r;
}
__device__ __forceinline__ float fast_rcp(float x) {
    float r;
    asm("rcp.approx.f32 %0, %1;" : "=f"(r) : "f"(x));
    return r;
}

#define BARN(id, cnt) asm volatile("bar.sync %0, %1;" :: "r"(id), "r"(cnt) : "memory")

// =====================================================================
// Forward: 128 CTAs x 192 threads = 2 teams x 96. Each team advances
// TWO independent batches (A, B) per loop iteration, sharing the same
// coefficient registers; the two matvecs interleave so one batch's
// serial latency (LDS -> FMA chain -> shfl -> STS -> bar) is hidden by
// the other's arithmetic within the same warp.
// Tiling per batch = R7: thread idx owns columns {2cp,2cp+1} on K-half
// h (lane-alternating -> 2-phase broadcast LDS.128), finalizes column
// idx after shfl.xor(1). Unnormalized exp domain; per-batch normalizer
// r = rcp(u[0]) published pre-reciprocated; exact shift S -= log(r).
// One team barrier per step.
// =====================================================================
__global__ __launch_bounds__(FWD_THREADS, 1) void crf_forward_kernel(
    const float* __restrict__ em,
    const int* __restrict__ masks,
    const float* __restrict__ start,
    const float* __restrict__ endt,
    const float* __restrict__ trans)
{
    const int team = threadIdx.x / TEAM_THREADS;
    const int idx  = threadIdx.x - team * TEAM_THREADS;   // 0..95 = my column
    const int cp = idx >> 1;
    const int h  = idx & 1;
    const int colA = 2 * cp, colB = 2 * cp + 1;
    const int bA = blockIdx.x * (2 * TEAMS) + 2 * team;
    const int bB = bA + 1;

    __shared__ __align__(16) float s_u[2][TEAMS][2][CC];
    __shared__ float s_r[2][TEAMS][2];

    // Coefficients: expT rows [48h,48h+48) for columns colA, colB,
    // packed over state pairs. SHARED between the two batches. 96 regs.
    u64 cA[24], cB[24];
#pragma unroll
    for (int m = 0; m < 24; m++) {
        int row = 48 * h + 2 * m;
        const float* r0 = trans + row * CC;
        const float* r1 = trans + (row + 1) * CC;
        cA[m] = pack2(__expf(r0[colA]), __expf(r1[colA]));
        cB[m] = pack2(__expf(r0[colB]), __expf(r1[colB]));
    }

    const float* emA = em + (size_t)bA * SS * CC + idx;
    const float* emB = em + (size_t)bB * SS * CC + idx;
    const int* mkA = masks + (size_t)bA * SS;
    const int* mkB = masks + (size_t)bB * SS;

    // ---- t = 0 ----
    const float st = start[idx];
    float uA = __expf(st + emA[0]);
    float uB = __expf(st + emB[0]);
    s_u[0][team][0][idx] = uA;
    s_u[0][team][1][idx] = uB;
    float SA = 0.f, SB = 0.f;
    if (idx == 0) {
        s_r[0][team][0] = fast_rcp(uA);
        s_r[0][team][1] = fast_rcp(uB);
    }

    // prefetch pipeline (distance 2)
    float EA = __expf(emA[1 * CC]);
    float EB = __expf(emB[1 * CC]);
    float enA = emA[2 * CC];
    float enB = emB[2 * CC];
    int mcA = mkA[1], mcB = mkB[1];
    int mnA = mkA[2], mnB = mkB[2];
    BARN(team, TEAM_THREADS);

    int p = 0;
    for (int t = 1; t < SS; t++) {
        float rA = s_r[p][team][0];
        float rB = s_r[p][team][1];

        int pf = t + 2 < SS ? t + 2 : SS - 1;
        float epA = emA[(size_t)pf * CC];
        float epB = emB[(size_t)pf * CC];
        int mpA = mkA[pf], mpB = mkB[pf];

        // interleaved matvecs: 8 independent FMA chains
        const ulonglong2* pvA = reinterpret_cast<const ulonglong2*>(&s_u[p][team][0][48 * h]);
        const ulonglong2* pvB = reinterpret_cast<const ulonglong2*>(&s_u[p][team][1][48 * h]);
        u64 qa0 = 0ull, qa1 = 0ull, qb0 = 0ull, qb1 = 0ull;
        u64 qc0 = 0ull, qc1 = 0ull, qd0 = 0ull, qd1 = 0ull;
#pragma unroll
        for (int k = 0; k < 12; k++) {
            ulonglong2 pa = pvA[k];
            ulonglong2 pb = pvB[k];
            fmadd2(qa0, pa.x, cA[2 * k]);
            fmadd2(qa1, pa.y, cA[2 * k + 1]);
            fmadd2(qb0, pa.x, cB[2 * k]);
            fmadd2(qb1, pa.y, cB[2 * k + 1]);
            fmadd2(qc0, pb.x, cA[2 * k]);
            fmadd2(qc1, pb.y, cA[2 * k + 1]);
            fmadd2(qd0, pb.x, cB[2 * k]);
            fmadd2(qd1, pb.y, cB[2 * k + 1]);
        }
        float2 fa = unpack2(add2(qa0, qa1));   // batch A, colA partial
        float2 fb = unpack2(add2(qb0, qb1));   // batch A, colB partial
        float2 fc = unpack2(add2(qc0, qc1));   // batch B, colA partial
        float2 fd = unpack2(add2(qd0, qd1));   // batch B, colB partial
        float wAa = fa.x + fa.y, wAb = fb.x + fb.y;
        float wBa = fc.x + fc.y, wBb = fd.x + fd.y;

        // combine K-halves; finalize column idx for both batches
        float mineA  = h ? wAb : wAa;
        float otherA = h ? wAa : wAb;
        float qA = mineA + __shfl_xor_sync(0xFFFFFFFFu, otherA, 1);
        float mineB  = h ? wBb : wBa;
        float otherB = h ? wBa : wBb;
        float qB = mineB + __shfl_xor_sync(0xFFFFFFFFu, otherB, 1);

        float unA = qA * (EA * rA);
        float unB = qB * (EB * rB);
        uA = mcA ? unA : uA;
        uB = mcB ? unB : uB;
        s_u[p ^ 1][team][0][idx] = uA;
        s_u[p ^ 1][team][1][idx] = uB;
        if (idx == 0) {
            s_r[p ^ 1][team][0] = fast_rcp(uA);
            s_r[p ^ 1][team][1] = fast_rcp(uB);
            SA = mcA ? SA - __logf(rA) : SA;
            SB = mcB ? SB - __logf(rB) : SB;
        }

        // rotate prefetch
        EA = __expf(enA);
        EB = __expf(enB);
        enA = epA;
        enB = epB;
        mcA = mnA; mcB = mnB;
        mnA = mpA; mnB = mpB;

        BARN(team, TEAM_THREADS);
        p ^= 1;
    }

    // denominator = S + log(sum_j u_j * exp(end_j)) per batch
    float ev = __expf(endt[idx]);
    s_u[p][team][0][idx] = uA * ev;
    s_u[p][team][1][idx] = uB * ev;
    BARN(team, TEAM_THREADS);
    if (idx == 0) {
        float sa = 0.f, sb = 0.f;
#pragma unroll
        for (int i = 0; i < CC; i++) {
            sa += s_u[p][team][0][i];
            sb += s_u[p][team][1][i];
        }
        g_den[bA] = SA + __logf(sa);
        g_den[bB] = SB + __logf(sb);
    }
}

// =====================================================================
// Numerator: one CTA (128 threads) per batch.
// =====================================================================
__global__ __launch_bounds__(128) void crf_num_kernel(
    const float* __restrict__ em,
    const int* __restrict__ tags,
    const int* __restrict__ masks,
    const float* __restrict__ start,
    const float* __restrict__ endt,
    const float* __restrict__ trans)
{
    const int b = blockIdx.x;
    const int tid = threadIdx.x;
    const int* tg = tags + (size_t)b * SS;
    const int* mk = masks + (size_t)b * SS;
    const float* e = em + (size_t)b * SS * CC;

    float s = 0.f;
    int cnt = 0;
#pragma unroll
    for (int it = 0; it < SS / 128; it++) {
        int t = tid + it * 128;
        int tagt = tg[t];
        int m = mk[t];
        cnt += m ? 1 : 0;
        if (t == 0) {
            s += start[tagt] + e[tagt];
        } else if (m) {
            int tp = tg[t - 1];
            s += trans[tp * CC + tagt] + e[(size_t)t * CC + tagt];
        }
    }
    __shared__ float ss[4];
    __shared__ int sc[4];
#pragma unroll
    for (int o = 16; o; o >>= 1) {
        s += __shfl_xor_sync(0xFFFFFFFFu, s, o);
        cnt += __shfl_xor_sync(0xFFFFFFFFu, cnt, o);
    }
    int wv = tid >> 5, lane = tid & 31;
    if (lane == 0) { ss[wv] = s; sc[wv] = cnt; }
    __syncthreads();
    if (tid == 0) {
        float st = ss[0] + ss[1] + ss[2] + ss[3];
        int ct = sc[0] + sc[1] + sc[2] + sc[3];
        int lt = tg[ct - 1];
        g_num[b] = st + endt[lt];
    }
}

// =====================================================================
// Final mean reduce
// =====================================================================
__global__ void crf_reduce_kernel(float* __restrict__ out)
{
    __shared__ float sh[BB];
    int t = threadIdx.x;
    sh[t] = g_num[t] - g_den[t];
    __syncthreads();
#pragma unroll
    for (int o = BB / 2; o > 0; o >>= 1) {
        if (t < o) sh[t] += sh[t + o];
        __syncthreads();
    }
    if (t == 0) out[0] = sh[0] * (1.0f / (float)BB);
}

extern "C" void kernel_launch(void* const* d_in, const int* in_sizes, int n_in,
                              void* d_out, int out_size)
{
    const float* em    = (const float*)d_in[0];
    const int*   tags  = (const int*)d_in[1];
    const int*   masks = (const int*)d_in[2];
    const float* start = (const float*)d_in[3];
    const float* endt  = (const float*)d_in[4];
    const float* trans = (const float*)d_in[5];
    float* out = (float*)d_out;

    crf_forward_kernel<<<BB / (2 * TEAMS), FWD_THREADS>>>(em, masks, start, endt, trans);
    crf_num_kernel<<<BB, 128>>>(em, tags, masks, start, endt, trans);
    crf_reduce_kernel<<<1, BB>>>(out);
}